// round 1
// baseline (speedup 1.0000x reference)
#include <cuda_runtime.h>
#include <math.h>

// Problem constants (fixed shapes from reference)
#define NB   64          // batch
#define NC   64          // channels
#define NH   64          // height
#define NW   64          // width
#define NI   256         // num instances
#define NK   576         // K = 64*3*3  (c, fh, fw)
#define NOH  32          // output height
#define NOW  32          // output width
#define KCHUNK 288       // K staged in 2 chunks through smem

// Scratch (device globals — allocation-free rule)
__device__ __align__(16) float g_expX[NB * NC * NH * NW];   // exp(x), 64 MB
__device__ __align__(16) float g_expO_T[NK * NI];           // exp(offsets) transposed [k][i]

// ---------------------------------------------------------------------------
// Kernel 1: expX = exp(x), elementwise (memory bound)
// ---------------------------------------------------------------------------
__global__ void k_exp_x(const float* __restrict__ x) {
    int i = blockIdx.x * 256 + threadIdx.x;   // grid covers exactly NB*NC*NH*NW
    g_expX[i] = expf(x[i]);
}

// ---------------------------------------------------------------------------
// Kernel 2: expO_T[k][i] = exp(offsets[i][k])   (tiny: 147456 elems)
// ---------------------------------------------------------------------------
__global__ void k_exp_o(const float* __restrict__ offsets) {
    int t = blockIdx.x * 256 + threadIdx.x;   // t = i*NK + k
    int i = t / NK;
    int k = t - i * NK;
    g_expO_T[k * NI + i] = expf(offsets[t]);
}

// ---------------------------------------------------------------------------
// Kernel 3: implicit-im2col GEMM in exp domain + log epilogue.
// Block = (oh, b): M-tile = 32 (all ow), N-tile = 256 (all instances).
// 256 threads: tm = tid/32 picks 4 consecutive m (ow), ti = tid%32 picks
// 8 i's as two float4 groups {4*ti .. 4*ti+3} and {128+4*ti .. 128+4*ti+3}.
// ---------------------------------------------------------------------------
__global__ void __launch_bounds__(256, 2) k_mex(float* __restrict__ out) {
    __shared__ __align__(16) float sP[KCHUNK][NOW];   // 36 KB patch chunk [k_local][m]

    const int oh  = blockIdx.x;       // 0..31
    const int b   = blockIdx.y;       // 0..63
    const int tid = threadIdx.x;
    const int tm  = tid >> 5;         // 0..7  -> m = tm*4 + j
    const int ti  = tid & 31;         // 0..31 -> i fragments

    float acc[4][8];
#pragma unroll
    for (int j = 0; j < 4; ++j)
#pragma unroll
        for (int u = 0; u < 8; ++u) acc[j][u] = 0.0f;

    const int ih0 = oh * 2 - 1;

#pragma unroll 1
    for (int kc = 0; kc < NK / KCHUNK; ++kc) {
        __syncthreads();   // protect previous chunk reads before overwrite

        // ---- fill patch chunk: sP[kl][m] = expX at (c,fh,fw) for pixel (b,oh,m)
        // padding (ih<0 or iw<0) contributes exp(0) = 1.0
#pragma unroll 1
        for (int t = tid; t < KCHUNK * NOW; t += 256) {
            int kl = t >> 5;            // 0..287
            int m  = t & 31;            // ow
            int k  = kc * KCHUNK + kl;  // global k = c*9 + fh*3 + fw
            int c  = k / 9;
            int r  = k - c * 9;
            int fh = r / 3;
            int fw = r - fh * 3;
            int ih = ih0 + fh;          // in [-1, 63]
            int iw = m * 2 - 1 + fw;    // in [-1, 63]
            float v = 1.0f;
            if (ih >= 0 && iw >= 0)
                v = g_expX[((b * NC + c) * NH + ih) * NW + iw];
            sP[kl][m] = v;
        }
        __syncthreads();

        // ---- GEMM over this K chunk
        const float* oBase = g_expO_T + kc * KCHUNK * NI;
#pragma unroll 4
        for (int kl = 0; kl < KCHUNK; ++kl) {
            // broadcast LDS.128: 4 consecutive m values for this warp
            const float4 p = *reinterpret_cast<const float4*>(&sP[kl][tm * 4]);
            const float4* orow = reinterpret_cast<const float4*>(oBase + kl * NI);
            const float4 b0 = orow[ti];        // i = 4*ti .. 4*ti+3
            const float4 b1 = orow[32 + ti];   // i = 128+4*ti .. 128+4*ti+3

            const float pv[4] = {p.x, p.y, p.z, p.w};
            const float bv[8] = {b0.x, b0.y, b0.z, b0.w, b1.x, b1.y, b1.z, b1.w};
#pragma unroll
            for (int j = 0; j < 4; ++j)
#pragma unroll
                for (int u = 0; u < 8; ++u)
                    acc[j][u] = fmaf(pv[j], bv[u], acc[j][u]);
        }
    }

    // ---- epilogue: y = log(S) - log(K); out layout (B, NI, OH, OW)
    const float lnK = logf((float)NK);
#pragma unroll
    for (int u = 0; u < 8; ++u) {
        int i = (u < 4) ? (ti * 4 + u) : (128 + ti * 4 + (u - 4));
        float4 v;
        v.x = logf(acc[0][u]) - lnK;
        v.y = logf(acc[1][u]) - lnK;
        v.z = logf(acc[2][u]) - lnK;
        v.w = logf(acc[3][u]) - lnK;
        // 4 consecutive ow at ow0 = tm*4
        *reinterpret_cast<float4*>(
            &out[(((b * NI + i) * NOH) + oh) * NOW + tm * 4]) = v;
    }
}

// ---------------------------------------------------------------------------
extern "C" void kernel_launch(void* const* d_in, const int* in_sizes, int n_in,
                              void* d_out, int out_size) {
    const float* x       = (const float*)d_in[0];   // (64,64,64,64) fp32
    const float* offsets = (const float*)d_in[1];   // (1,256,64,3,3) fp32
    float* out           = (float*)d_out;           // (64,256,32,32) fp32

    k_exp_x<<<(NB * NC * NH * NW) / 256, 256>>>(x);
    k_exp_o<<<(NK * NI) / 256, 256>>>(offsets);

    dim3 grid(NOH, NB);
    k_mex<<<grid, 256>>>(out);
}

// round 3
// speedup vs baseline: 3.3391x; 3.3391x over previous
#include <cuda_runtime.h>
#include <cuda_bf16.h>
#include <cstdint>
#include <math.h>

// ---------------- problem constants ----------------
#define NB    64
#define NCH   64
#define NI    256
#define NKTOT 576          // 64 ch * 9 taps ; reordered k' = r*64 + c
#define PADW  66           // (H+2) halo for pad-1
#define LNK   6.35610766f  // ln(576)

// ---------------- GEMM tiling ----------------
#define STAGES   3
#define ACHUNK   16384     // A tile: 128 rows x 128B
#define BCHUNK   32768     // B tile: 256 rows x 128B
#define STG_SZ   (ACHUNK + BCHUNK)              // 49152
#define SMEM_TOTAL (STAGES * STG_SZ)            // 147456

// ---------------- device scratch (allocation-free rule) ----------------
__device__ __align__(16) __nv_bfloat16 g_eh[(size_t)NB * PADW * PADW * NCH]; // exp(x) hi
__device__ __align__(16) __nv_bfloat16 g_el[(size_t)NB * PADW * PADW * NCH]; // exp(x) lo
__device__ __align__(16) __nv_bfloat16 g_Bh[NI * NKTOT];                     // exp(off) hi [i][r*64+c]
__device__ __align__(16) __nv_bfloat16 g_Bl[NI * NKTOT];

// ---------------- helpers ----------------
__device__ __forceinline__ uint32_t smem_u32(const void* p) {
    uint32_t a;
    asm("{ .reg .u64 t; cvta.to.shared.u64 t, %1; cvt.u32.u64 %0, t; }" : "=r"(a) : "l"(p));
    return a;
}
__device__ __forceinline__ uint32_t swz(uint32_t o) { return o ^ ((o >> 3) & 0x70); }

__device__ __forceinline__ void cp16(uint32_t dst, const void* src) {
    asm volatile("cp.async.cg.shared.global [%0], [%1], 16;" :: "r"(dst), "l"(src));
}

#define LDSM4(r, a)                                                                     \
    asm volatile("ldmatrix.sync.aligned.m8n8.x4.shared.b16 {%0,%1,%2,%3}, [%4];"        \
        : "=r"((r)[0]), "=r"((r)[1]), "=r"((r)[2]), "=r"((r)[3]) : "r"(a))

#define MMA16816(d, a, b0, b1)                                                          \
    asm volatile("mma.sync.aligned.m16n8k16.row.col.f32.bf16.bf16.f32 "                 \
        "{%0,%1,%2,%3}, {%4,%5,%6,%7}, {%8,%9}, {%0,%1,%2,%3};"                         \
        : "+f"((d)[0]), "+f"((d)[1]), "+f"((d)[2]), "+f"((d)[3])                        \
        : "r"((a)[0]), "r"((a)[1]), "r"((a)[2]), "r"((a)[3]), "r"(b0), "r"(b1))

// ===========================================================================
// Prep 1: halo borders (pad contributes exp(0)=1 -> hi=1.0, lo=0)
// ===========================================================================
__global__ void k_border() {
    int t = blockIdx.x * 256 + threadIdx.x;       // < 64*2*66*64 = 540672
    int c    = t & 63;
    int rest = t >> 6;
    int pos  = rest % PADW;
    int be   = rest / PADW;
    int e = be & 1, b = be >> 1;
    size_t off;
    if (e == 0) off = (((size_t)b * PADW + 0) * PADW + pos) * NCH + c;   // top row
    else        off = (((size_t)b * PADW + pos) * PADW + 0) * NCH + c;   // left col
    g_eh[off] = __float2bfloat16(1.0f);
    g_el[off] = __float2bfloat16(0.0f);
}

// ===========================================================================
// Prep 2: exp(x), hi/lo split, transpose (B,C,H,W) -> (B,H+2,W+2,C) interior
// ===========================================================================
__global__ void k_prep_x(const float* __restrict__ x) {
    __shared__ float tile[64][65];
    const int b = blockIdx.y, h = blockIdx.x, t = threadIdx.x;
#pragma unroll
    for (int i = 0; i < 16; ++i) {
        int idx = t + i * 256;
        int c = idx >> 6, w = idx & 63;
        tile[c][w] = x[(((size_t)(b * 64 + c) * 64 + h) << 6) + w];
    }
    __syncthreads();
#pragma unroll
    for (int i = 0; i < 16; ++i) {
        int idx = t + i * 256;
        int w = idx >> 6, c = idx & 63;
        float v = __expf(tile[c][w]);
        __nv_bfloat16 hi = __float2bfloat16(v);
        float lo = v - __bfloat162float(hi);
        size_t off = (((size_t)b * PADW + (h + 1)) * PADW + (w + 1)) * NCH + c;
        g_eh[off] = hi;
        g_el[off] = __float2bfloat16(lo);
    }
}

// ===========================================================================
// Prep 3: exp(offsets), hi/lo split, reorder k = c*9+r  ->  k' = r*64+c
// ===========================================================================
__global__ void k_prep_o(const float* __restrict__ off) {
    int t = blockIdx.x * 256 + threadIdx.x;  // < 256*576 = 147456
    int i  = t / NKTOT;
    int kp = t - i * NKTOT;
    int r = kp >> 6, c = kp & 63;
    float v = __expf(off[i * NKTOT + c * 9 + r]);
    __nv_bfloat16 hi = __float2bfloat16(v);
    g_Bh[t] = hi;
    g_Bl[t] = __float2bfloat16(v - __bfloat162float(hi));
}

// ===========================================================================
// Main GEMM: CTA 128(M pixels) x 256(N instances), 8 warps 2x4, warp 64x64.
// K = 27 chunks of 64: pass p in {hi*hi, lo*hi, hi*lo}, tap r in 0..8.
// ===========================================================================
__device__ __forceinline__ void load_chunk(int j, int s, uint32_t smb,
                                           int tid, int bb, int ohb) {
    int p = (j >= 18) ? 2 : ((j >= 9) ? 1 : 0);
    int r = j - p * 9;
    int fh = r / 3, fw = r - fh * 3;
    const __nv_bfloat16* Aarr = (p == 1) ? g_el : g_eh;
    const __nv_bfloat16* Barr = (p == 2) ? g_Bl : g_Bh;
    uint32_t sa = smb + s * STG_SZ;
    uint32_t sb = sa + ACHUNK;
    // A tile: 128 rows (pixels) x 64 ch = 1024 x 16B segments
#pragma unroll
    for (int it = 0; it < 4; ++it) {
        int idx = tid + it * 256;
        int l = idx >> 3, g = idx & 7;
        int ih1 = 2 * ohb + ((l >> 5) << 1) + fh;   // (oh*2-1+fh)+1
        int iw1 = ((l & 31) << 1) + fw;             // (ow*2-1+fw)+1
        const void* src = Aarr + ((((size_t)bb * PADW + ih1) * PADW + iw1) << 6) + (g << 3);
        cp16(sa + swz((l << 7) + (g << 4)), src);
    }
    // B tile: 256 rows (instances) x 64 k = 2048 x 16B segments
#pragma unroll
    for (int it = 0; it < 8; ++it) {
        int idx = tid + it * 256;
        int n = idx >> 3, g = idx & 7;
        const void* src = Barr + (size_t)n * NKTOT + (r << 6) + (g << 3);
        cp16(sb + swz((n << 7) + (g << 4)), src);
    }
    asm volatile("cp.async.commit_group;" ::: "memory");
}

__global__ void __launch_bounds__(256, 1) k_mex(float* __restrict__ out) {
    extern __shared__ __align__(1024) char sm[];
    const uint32_t smb = smem_u32(sm);
    const int tid  = threadIdx.x;
    const int wid  = tid >> 5, lane = tid & 31;
    const int bb   = blockIdx.x >> 3;           // batch
    const int ohb  = (blockIdx.x & 7) << 2;     // 4 output rows per tile
    const int wm   = wid >> 2;                  // 0..1  (m block of 64)
    const int wn   = wid & 3;                   // 0..3  (n block of 64)

    float acc[4][8][4];                          // [mt][n8 tile][d-regs]
#pragma unroll
    for (int a = 0; a < 4; ++a)
#pragma unroll
        for (int b = 0; b < 8; ++b)
#pragma unroll
            for (int c = 0; c < 4; ++c) acc[a][b][c] = 0.0f;

    // per-lane ldmatrix address components (row & 16B segment within row)
    const int rowA_l = (lane & 7) + (lane & 8);        // + mt*16 + wm*64
    const int segA_l = (lane & 16);                    // + ks*32
    const int rowB_l = (lane & 7) + ((lane & 16) >> 1);// + jj*16 + wn*64
    const int segB_l = ((lane & 8) << 1);              // + ks*32

    // prologue
    load_chunk(0, 0, smb, tid, bb, ohb);
    load_chunk(1, 1, smb, tid, bb, ohb);

#pragma unroll 1
    for (int j = 0; j < 27; ++j) {
        if (j < 26) asm volatile("cp.async.wait_group 1;" ::: "memory");
        else        asm volatile("cp.async.wait_group 0;" ::: "memory");
        __syncthreads();

        if (j + 2 < 27) load_chunk(j + 2, (j + 2) % 3, smb, tid, bb, ohb);

        const uint32_t sa = smb + (j % 3) * STG_SZ;
        const uint32_t sb = sa + ACHUNK;

#pragma unroll
        for (int ks = 0; ks < 4; ++ks) {
            uint32_t af[4][4], bf[4][4];
#pragma unroll
            for (int mt = 0; mt < 4; ++mt) {
                int row = wm * 64 + mt * 16 + rowA_l;
                uint32_t byo = (uint32_t)(ks * 32 + segA_l) ^ ((row & 7) << 4);
                LDSM4(af[mt], sa + row * 128 + byo);
            }
#pragma unroll
            for (int jj = 0; jj < 4; ++jj) {
                int row = wn * 64 + jj * 16 + rowB_l;
                uint32_t byo = (uint32_t)(ks * 32 + segB_l) ^ ((row & 7) << 4);
                LDSM4(bf[jj], sb + row * 128 + byo);
            }
#pragma unroll
            for (int mt = 0; mt < 4; ++mt)
#pragma unroll
                for (int jj = 0; jj < 4; ++jj) {
                    MMA16816(acc[mt][2 * jj],     af[mt], bf[jj][0], bf[jj][1]);
                    MMA16816(acc[mt][2 * jj + 1], af[mt], bf[jj][2], bf[jj][3]);
                }
        }
    }

    // epilogue: y = log(S) - ln(576); out layout (B, NI, 32, 32)
    const int g  = lane >> 2;
    const int tc = lane & 3;
    float* ob = out + ((size_t)bb << 18);
#pragma unroll
    for (int mt = 0; mt < 4; ++mt) {
#pragma unroll
        for (int jj = 0; jj < 8; ++jj) {
            const int i0 = wn * 64 + jj * 8 + 2 * tc;
#pragma unroll
            for (int r = 0; r < 4; ++r) {
                int m = wm * 64 + mt * 16 + g + ((r >> 1) << 3);
                int i = i0 + (r & 1);
                float y = __logf(acc[mt][jj][r]) - LNK;
                ob[((size_t)i << 10) + ((ohb + (m >> 5)) << 5) + (m & 31)] = y;
            }
        }
    }
}

// ===========================================================================
extern "C" void kernel_launch(void* const* d_in, const int* in_sizes, int n_in,
                              void* d_out, int out_size) {
    const float* x   = (const float*)d_in[0];   // (64,64,64,64)
    const float* off = (const float*)d_in[1];   // (1,256,64,3,3)
    float* out       = (float*)d_out;           // (64,256,32,32)

    k_border<<<2112, 256>>>();
    dim3 gx(64, 64);                            // (h, b)
    k_prep_x<<<gx, 256>>>(x);
    k_prep_o<<<576, 256>>>(off);

    cudaFuncSetAttribute(k_mex, cudaFuncAttributeMaxDynamicSharedMemorySize, SMEM_TOTAL);
    k_mex<<<512, 256, SMEM_TOTAL>>>(out);
}

// round 4
// speedup vs baseline: 4.9915x; 1.4948x over previous
#include <cuda_runtime.h>
#include <cuda_fp16.h>
#include <cstdint>
#include <math.h>

// ---------------- problem constants ----------------
#define NB    64
#define NCH   64
#define NI    256
#define NKTOT 576          // 64 ch * 9 taps ; reordered k' = r*64 + c
#define PADW  66           // (H+2) halo for pad-1
#define LNK   6.35610766f  // ln(576)

// ---------------- GEMM tiling ----------------
// stage = { A_hi 16KB | A_lo 16KB | B 32KB } for one tap (K-chunk of 64)
#define STAGES   3
#define AOFF_LO  16384
#define BOFF     32768
#define STG_SZ   65536
#define SMEM_TOTAL (STAGES * STG_SZ)            // 196608

// ---------------- device scratch (allocation-free rule) ----------------
__device__ __align__(16) __half g_eh[(size_t)NB * PADW * PADW * NCH]; // exp(x) hi
__device__ __align__(16) __half g_el[(size_t)NB * PADW * PADW * NCH]; // exp(x) lo
__device__ __align__(16) __half g_Bh[NI * NKTOT];                     // exp(off) hi [i][r*64+c]

// ---------------- helpers ----------------
__device__ __forceinline__ uint32_t smem_u32(const void* p) {
    uint32_t a;
    asm("{ .reg .u64 t; cvta.to.shared.u64 t, %1; cvt.u32.u64 %0, t; }" : "=r"(a) : "l"(p));
    return a;
}
__device__ __forceinline__ uint32_t swz(uint32_t o) { return o ^ ((o >> 3) & 0x70); }

__device__ __forceinline__ void cp16(uint32_t dst, const void* src) {
    asm volatile("cp.async.cg.shared.global [%0], [%1], 16;" :: "r"(dst), "l"(src));
}

#define LDSM4(r, a)                                                                     \
    asm volatile("ldmatrix.sync.aligned.m8n8.x4.shared.b16 {%0,%1,%2,%3}, [%4];"        \
        : "=r"((r)[0]), "=r"((r)[1]), "=r"((r)[2]), "=r"((r)[3]) : "r"(a))

#define MMA16816(d, a, b0, b1)                                                          \
    asm volatile("mma.sync.aligned.m16n8k16.row.col.f32.f16.f16.f32 "                   \
        "{%0,%1,%2,%3}, {%4,%5,%6,%7}, {%8,%9}, {%0,%1,%2,%3};"                         \
        : "+f"((d)[0]), "+f"((d)[1]), "+f"((d)[2]), "+f"((d)[3])                        \
        : "r"((a)[0]), "r"((a)[1]), "r"((a)[2]), "r"((a)[3]), "r"(b0), "r"(b1))

// ===========================================================================
// Prep 1: halo borders (pad contributes exp(0)=1 -> hi=1.0, lo=0)
// ===========================================================================
__global__ void k_border() {
    int t = blockIdx.x * 256 + threadIdx.x;       // < 64*2*66*64 = 540672
    int c    = t & 63;
    int rest = t >> 6;
    int pos  = rest % PADW;
    int be   = rest / PADW;
    int e = be & 1, b = be >> 1;
    size_t off;
    if (e == 0) off = (((size_t)b * PADW + 0) * PADW + pos) * NCH + c;   // top row
    else        off = (((size_t)b * PADW + pos) * PADW + 0) * NCH + c;   // left col
    g_eh[off] = __float2half_rn(1.0f);
    g_el[off] = __float2half_rn(0.0f);
}

// ===========================================================================
// Prep 2: exp(x), fp16 hi/lo split, transpose (B,C,H,W) -> (B,H+2,W+2,C)
// ===========================================================================
__global__ void k_prep_x(const float* __restrict__ x) {
    __shared__ float tile[64][65];
    const int b = blockIdx.y, h = blockIdx.x, t = threadIdx.x;
#pragma unroll
    for (int i = 0; i < 16; ++i) {
        int idx = t + i * 256;
        int c = idx >> 6, w = idx & 63;
        tile[c][w] = x[(((size_t)(b * 64 + c) * 64 + h) << 6) + w];
    }
    __syncthreads();
#pragma unroll
    for (int i = 0; i < 16; ++i) {
        int idx = t + i * 256;
        int w = idx >> 6, c = idx & 63;
        float v = __expf(tile[c][w]);
        __half hi = __float2half_rn(v);
        float lo = v - __half2float(hi);
        size_t off = (((size_t)b * PADW + (h + 1)) * PADW + (w + 1)) * NCH + c;
        g_eh[off] = hi;
        g_el[off] = __float2half_rn(lo);
    }
}

// ===========================================================================
// Prep 3: exp(offsets) fp16, reorder k = c*9+r  ->  k' = r*64+c
// ===========================================================================
__global__ void k_prep_o(const float* __restrict__ off) {
    int t = blockIdx.x * 256 + threadIdx.x;  // < 256*576 = 147456
    int i  = t / NKTOT;
    int kp = t - i * NKTOT;
    int r = kp >> 6, c = kp & 63;
    g_Bh[t] = __float2half_rn(__expf(off[i * NKTOT + c * 9 + r]));
}

// ===========================================================================
// Main GEMM: CTA 128(M pixels) x 256(N instances), 8 warps 2x4, warp 64x64.
// 9 taps; per tap: pass hi (A_hi*B) + pass lo (A_lo*B), B fragments reused.
// ===========================================================================
__device__ __forceinline__ void load_chunk(int r, int s, uint32_t smb,
                                           int tid, int bb, int ohb) {
    int fh = r / 3, fw = r - fh * 3;
    uint32_t sah = smb + s * STG_SZ;
    uint32_t sal = sah + AOFF_LO;
    uint32_t sb  = sah + BOFF;
    // A tiles (hi & lo): 128 rows (pixels) x 64 ch = 1024 x 16B segments each
#pragma unroll
    for (int it = 0; it < 4; ++it) {
        int idx = tid + it * 256;
        int l = idx >> 3, g = idx & 7;
        int ih1 = 2 * ohb + ((l >> 5) << 1) + fh;   // (oh*2-1+fh)+1
        int iw1 = ((l & 31) << 1) + fw;             // (ow*2-1+fw)+1
        size_t eo = ((((size_t)bb * PADW + ih1) * PADW + iw1) << 6) + (g << 3);
        uint32_t so = swz((l << 7) + (g << 4));
        cp16(sah + so, g_eh + eo);
        cp16(sal + so, g_el + eo);
    }
    // B tile: 256 rows (instances) x 64 k = 2048 x 16B segments
#pragma unroll
    for (int it = 0; it < 8; ++it) {
        int idx = tid + it * 256;
        int n = idx >> 3, g = idx & 7;
        const void* src = g_Bh + (size_t)n * NKTOT + (r << 6) + (g << 3);
        cp16(sb + swz((n << 7) + (g << 4)), src);
    }
    asm volatile("cp.async.commit_group;" ::: "memory");
}

__global__ void __launch_bounds__(256, 1) k_mex(float* __restrict__ out) {
    extern __shared__ __align__(1024) char sm[];
    const uint32_t smb = smem_u32(sm);
    const int tid  = threadIdx.x;
    const int wid  = tid >> 5, lane = tid & 31;
    const int bb   = blockIdx.x >> 3;           // batch
    const int ohb  = (blockIdx.x & 7) << 2;     // 4 output rows per tile
    const int wm   = wid >> 2;                  // 0..1  (m block of 64)
    const int wn   = wid & 3;                   // 0..3  (n block of 64)

    float acc[4][8][4];                          // [mt][n8 tile][d-regs]
#pragma unroll
    for (int a = 0; a < 4; ++a)
#pragma unroll
        for (int b = 0; b < 8; ++b)
#pragma unroll
            for (int c = 0; c < 4; ++c) acc[a][b][c] = 0.0f;

    // per-lane ldmatrix address components
    const int rowA_l = (lane & 7) + (lane & 8);        // + mt*16 + wm*64
    const int segA_l = (lane & 16);                    // + ks*32
    const int rowB_l = (lane & 7) + ((lane & 16) >> 1);// + jj*16 + wn*64
    const int segB_l = ((lane & 8) << 1);              // + ks*32

    // prologue: prefetch taps 0,1
    load_chunk(0, 0, smb, tid, bb, ohb);
    load_chunk(1, 1, smb, tid, bb, ohb);

#pragma unroll 1
    for (int j = 0; j < 9; ++j) {
        if (j < 8) asm volatile("cp.async.wait_group 1;" ::: "memory");
        else       asm volatile("cp.async.wait_group 0;" ::: "memory");
        __syncthreads();

        if (j + 2 < 9) load_chunk(j + 2, (j + 2) % 3, smb, tid, bb, ohb);

        const uint32_t sah = smb + (j % 3) * STG_SZ;
        const uint32_t sal = sah + AOFF_LO;
        const uint32_t sb  = sah + BOFF;

#pragma unroll
        for (int ks = 0; ks < 4; ++ks) {
            uint32_t bf[4][4];
#pragma unroll
            for (int jj = 0; jj < 4; ++jj) {
                int row = wn * 64 + jj * 16 + rowB_l;
                uint32_t byo = (uint32_t)(ks * 32 + segB_l) ^ ((row & 7) << 4);
                LDSM4(bf[jj], sb + row * 128 + byo);
            }
#pragma unroll
            for (int mt = 0; mt < 4; ++mt) {
                int row = wm * 64 + mt * 16 + rowA_l;
                uint32_t byo = (uint32_t)(ks * 32 + segA_l) ^ ((row & 7) << 4);
                uint32_t af[4];
                LDSM4(af, sah + row * 128 + byo);       // hi pass
#pragma unroll
                for (int jj = 0; jj < 4; ++jj) {
                    MMA16816(acc[mt][2 * jj],     af, bf[jj][0], bf[jj][1]);
                    MMA16816(acc[mt][2 * jj + 1], af, bf[jj][2], bf[jj][3]);
                }
                LDSM4(af, sal + row * 128 + byo);       // lo pass (same B)
#pragma unroll
                for (int jj = 0; jj < 4; ++jj) {
                    MMA16816(acc[mt][2 * jj],     af, bf[jj][0], bf[jj][1]);
                    MMA16816(acc[mt][2 * jj + 1], af, bf[jj][2], bf[jj][3]);
                }
            }
        }
    }

    // epilogue: y = log(S) - ln(576); out layout (B, NI, 32, 32)
    const int g  = lane >> 2;
    const int tc = lane & 3;
    float* ob = out + ((size_t)bb << 18);
#pragma unroll
    for (int mt = 0; mt < 4; ++mt) {
#pragma unroll
        for (int jj = 0; jj < 8; ++jj) {
            const int i0 = wn * 64 + jj * 8 + 2 * tc;
#pragma unroll
            for (int r = 0; r < 4; ++r) {
                int m = wm * 64 + mt * 16 + g + ((r >> 1) << 3);
                int i = i0 + (r & 1);
                float y = __logf(acc[mt][jj][r]) - LNK;
                ob[((size_t)i << 10) + ((ohb + (m >> 5)) << 5) + (m & 31)] = y;
            }
        }
    }
}

// ===========================================================================
extern "C" void kernel_launch(void* const* d_in, const int* in_sizes, int n_in,
                              void* d_out, int out_size) {
    const float* x   = (const float*)d_in[0];   // (64,64,64,64)
    const float* off = (const float*)d_in[1];   // (1,256,64,3,3)
    float* out       = (float*)d_out;           // (64,256,32,32)

    k_border<<<2112, 256>>>();
    dim3 gx(64, 64);                            // (h, b)
    k_prep_x<<<gx, 256>>>(x);
    k_prep_o<<<576, 256>>>(off);

    cudaFuncSetAttribute(k_mex, cudaFuncAttributeMaxDynamicSharedMemorySize, SMEM_TOTAL);
    k_mex<<<512, 256, SMEM_TOTAL>>>(out);
}

// round 6
// speedup vs baseline: 5.0174x; 1.0052x over previous
#include <cuda_runtime.h>
#include <cuda_fp16.h>
#include <cstdint>
#include <math.h>

// ---------------- problem constants ----------------
#define NB    64
#define NCH   64
#define NI    256
#define NKTOT 576          // 64 ch * 9 taps ; reordered k' = r*64 + c
#define PADW  66           // (H+2) halo for pad-1
#define LNK   6.35610766f  // ln(576)

// ---------------- GEMM tiling ----------------
// stage = { A_hi 16KB | A_lo 16KB | B 32KB } for one tap (K-chunk of 64)
#define STAGES   3
#define AOFF_LO  16384
#define BOFF     32768
#define STG_SZ   65536
#define SMEM_TOTAL (STAGES * STG_SZ)            // 196608
#define NTHR     512

// ---------------- device scratch (allocation-free rule) ----------------
__device__ __align__(16) __half g_eh[(size_t)NB * PADW * PADW * NCH]; // exp(x) hi
__device__ __align__(16) __half g_el[(size_t)NB * PADW * PADW * NCH]; // exp(x) lo
__device__ __align__(16) __half g_Bh[NI * NKTOT];                     // exp(off) hi [i][r*64+c]

// ---------------- helpers ----------------
__device__ __forceinline__ uint32_t smem_u32(const void* p) {
    uint32_t a;
    asm("{ .reg .u64 t; cvta.to.shared.u64 t, %1; cvt.u32.u64 %0, t; }" : "=r"(a) : "l"(p));
    return a;
}
__device__ __forceinline__ uint32_t swz(uint32_t o) { return o ^ ((o >> 3) & 0x70); }

__device__ __forceinline__ void cp16(uint32_t dst, const void* src) {
    asm volatile("cp.async.cg.shared.global [%0], [%1], 16;" :: "r"(dst), "l"(src));
}

#define LDSM4(r, a)                                                                     \
    asm volatile("ldmatrix.sync.aligned.m8n8.x4.shared.b16 {%0,%1,%2,%3}, [%4];"        \
        : "=r"((r)[0]), "=r"((r)[1]), "=r"((r)[2]), "=r"((r)[3]) : "r"(a))

#define MMA16816(d, a, b0, b1)                                                          \
    asm volatile("mma.sync.aligned.m16n8k16.row.col.f32.f16.f16.f32 "                   \
        "{%0,%1,%2,%3}, {%4,%5,%6,%7}, {%8,%9}, {%0,%1,%2,%3};"                         \
        : "+f"((d)[0]), "+f"((d)[1]), "+f"((d)[2]), "+f"((d)[3])                        \
        : "r"((a)[0]), "r"((a)[1]), "r"((a)[2]), "r"((a)[3]), "r"(b0), "r"(b1))

// ===========================================================================
// Prep 1: halo borders, half2 stores (pad = exp(0)=1 -> hi=1, lo=0)
// ===========================================================================
__global__ void k_border() {
    int t = blockIdx.x * 256 + threadIdx.x;   // < 64*2*66*32 = 270336 half2's
    int c2   = t & 31;
    int rest = t >> 5;
    int pos  = rest % PADW;
    int be   = rest / PADW;
    int e = be & 1, b = be >> 1;
    size_t off2;
    if (e == 0) off2 = ((((size_t)b * PADW + 0) * PADW + pos) << 5) + c2;   // top row
    else        off2 = ((((size_t)b * PADW + pos) * PADW + 0) << 5) + c2;   // left col
    reinterpret_cast<__half2*>(g_eh)[off2] = __floats2half2_rn(1.0f, 1.0f);
    reinterpret_cast<__half2*>(g_el)[off2] = __floats2half2_rn(0.0f, 0.0f);
}

// ===========================================================================
// Prep 2: exp(x), fp16 hi/lo split, transpose (B,C,H,W) -> (B,H+2,W+2,C),
// half2 stores
// ===========================================================================
__global__ void k_prep_x(const float* __restrict__ x) {
    __shared__ float tile[64][66];            // [w][c], stride 66 (f2-aligned)
    const int b = blockIdx.y, h = blockIdx.x, t = threadIdx.x;
#pragma unroll
    for (int i = 0; i < 16; ++i) {
        int idx = t + i * 256;
        int c = idx >> 6, w = idx & 63;
        tile[w][c] = x[(((size_t)(b * 64 + c) * 64 + h) << 6) + w];
    }
    __syncthreads();
#pragma unroll
    for (int i = 0; i < 8; ++i) {
        int idx = t + i * 256;                // 2048 half2's
        int w = idx >> 5, c2 = idx & 31;
        float2 v = *reinterpret_cast<const float2*>(&tile[w][2 * c2]);
        float e0 = __expf(v.x), e1 = __expf(v.y);
        __half h0 = __float2half_rn(e0), h1 = __float2half_rn(e1);
        float l0 = e0 - __half2float(h0), l1 = e1 - __half2float(h1);
        size_t off2 = ((((size_t)b * PADW + (h + 1)) * PADW + (w + 1)) << 5) + c2;
        reinterpret_cast<__half2*>(g_eh)[off2] = __halves2half2(h0, h1);
        reinterpret_cast<__half2*>(g_el)[off2] =
            __floats2half2_rn(l0, l1);
    }
}

// ===========================================================================
// Prep 3: exp(offsets) fp16, reorder k = c*9+r  ->  k' = r*64+c
// ===========================================================================
__global__ void k_prep_o(const float* __restrict__ off) {
    int t = blockIdx.x * 256 + threadIdx.x;  // < 256*576 = 147456
    int i  = t / NKTOT;
    int kp = t - i * NKTOT;
    int r = kp >> 6, c = kp & 63;
    g_Bh[t] = __float2half_rn(__expf(off[i * NKTOT + c * 9 + r]));
}

// ===========================================================================
// Main GEMM: CTA 128(M) x 256(N), 16 warps 4x4, warp tile 32x64.
// 9 taps; per tap: hi pass (A_hi*B) + lo pass (A_lo*B), B frags reused.
// ===========================================================================
__device__ __forceinline__ void load_chunk(int r, int s, uint32_t smb,
                                           int tid, int bb, int ohb) {
    int fh = r / 3, fw = r - fh * 3;
    uint32_t sah = smb + s * STG_SZ;
    uint32_t sal = sah + AOFF_LO;
    uint32_t sb  = sah + BOFF;
    // A tiles (hi & lo): 128 rows x 8 segs = 1024 x 16B each
#pragma unroll
    for (int it = 0; it < 2; ++it) {
        int idx = tid + it * NTHR;
        int l = idx >> 3, g = idx & 7;
        int ih1 = 2 * ohb + ((l >> 5) << 1) + fh;   // (oh*2-1+fh)+1
        int iw1 = ((l & 31) << 1) + fw;             // (ow*2-1+fw)+1
        size_t eo = ((((size_t)bb * PADW + ih1) * PADW + iw1) << 6) + (g << 3);
        uint32_t so = swz((l << 7) + (g << 4));
        cp16(sah + so, g_eh + eo);
        cp16(sal + so, g_el + eo);
    }
    // B tile: 256 rows x 8 segs = 2048 x 16B
#pragma unroll
    for (int it = 0; it < 4; ++it) {
        int idx = tid + it * NTHR;
        int n = idx >> 3, g = idx & 7;
        const void* src = g_Bh + (size_t)n * NKTOT + (r << 6) + (g << 3);
        cp16(sb + swz((n << 7) + (g << 4)), src);
    }
    asm volatile("cp.async.commit_group;" ::: "memory");
}

__global__ void __launch_bounds__(NTHR, 1) k_mex(float* __restrict__ out) {
    extern __shared__ __align__(1024) char sm[];
    const uint32_t smb = smem_u32(sm);
    const int tid  = threadIdx.x;
    const int wid  = tid >> 5, lane = tid & 31;
    const int bb   = blockIdx.x >> 3;           // batch
    const int ohb  = (blockIdx.x & 7) << 2;     // 4 output rows per tile
    const int wm   = wid >> 2;                  // 0..3  (m block of 32)
    const int wn   = wid & 3;                   // 0..3  (n block of 64)

    float acc[2][8][4];                          // [mt][n8 tile][d-regs]
#pragma unroll
    for (int a = 0; a < 2; ++a)
#pragma unroll
        for (int b = 0; b < 8; ++b)
#pragma unroll
            for (int c = 0; c < 4; ++c) acc[a][b][c] = 0.0f;

    // per-lane ldmatrix address components
    const int rowA_l = (lane & 7) + (lane & 8);        // + mt*16 + wm*32
    const int segA_l = (lane & 16);                    // + ks*32
    const int rowB_l = (lane & 7) + ((lane & 16) >> 1);// + jj*16 + wn*64
    const int segB_l = ((lane & 8) << 1);              // + ks*32

    // prologue: prefetch taps 0,1
    load_chunk(0, 0, smb, tid, bb, ohb);
    load_chunk(1, 1, smb, tid, bb, ohb);

#pragma unroll 1
    for (int j = 0; j < 9; ++j) {
        if (j < 8) asm volatile("cp.async.wait_group 1;" ::: "memory");
        else       asm volatile("cp.async.wait_group 0;" ::: "memory");
        __syncthreads();

        if (j + 2 < 9) load_chunk(j + 2, (j + 2) % 3, smb, tid, bb, ohb);

        const uint32_t sah = smb + (j % 3) * STG_SZ;
        const uint32_t sal = sah + AOFF_LO;
        const uint32_t sb  = sah + BOFF;

#pragma unroll
        for (int ks = 0; ks < 4; ++ks) {
            uint32_t bf[4][4];
#pragma unroll
            for (int jj = 0; jj < 4; ++jj) {
                int row = wn * 64 + jj * 16 + rowB_l;
                uint32_t byo = (uint32_t)(ks * 32 + segB_l) ^ ((row & 7) << 4);
                LDSM4(bf[jj], sb + row * 128 + byo);
            }
#pragma unroll
            for (int mt = 0; mt < 2; ++mt) {
                int row = wm * 32 + mt * 16 + rowA_l;
                uint32_t byo = (uint32_t)(ks * 32 + segA_l) ^ ((row & 7) << 4);
                uint32_t af[4];
                LDSM4(af, sah + row * 128 + byo);       // hi pass
#pragma unroll
                for (int jj = 0; jj < 4; ++jj) {
                    MMA16816(acc[mt][2 * jj],     af, bf[jj][0], bf[jj][1]);
                    MMA16816(acc[mt][2 * jj + 1], af, bf[jj][2], bf[jj][3]);
                }
                LDSM4(af, sal + row * 128 + byo);       // lo pass (same B)
#pragma unroll
                for (int jj = 0; jj < 4; ++jj) {
                    MMA16816(acc[mt][2 * jj],     af, bf[jj][0], bf[jj][1]);
                    MMA16816(acc[mt][2 * jj + 1], af, bf[jj][2], bf[jj][3]);
                }
            }
        }
    }

    // epilogue: y = log(S) - ln(576); out layout (B, NI, 32, 32)
    const int g  = lane >> 2;
    const int tc = lane & 3;
    float* ob = out + ((size_t)bb << 18);
#pragma unroll
    for (int mt = 0; mt < 2; ++mt) {
#pragma unroll
        for (int jj = 0; jj < 8; ++jj) {
            const int i0 = wn * 64 + jj * 8 + 2 * tc;
#pragma unroll
            for (int r = 0; r < 4; ++r) {
                int m = wm * 32 + mt * 16 + g + ((r >> 1) << 3);
                int i = i0 + (r & 1);
                float y = __logf(acc[mt][jj][r]) - LNK;
                ob[((size_t)i << 10) + ((ohb + (m >> 5)) << 5) + (m & 31)] = y;
            }
        }
    }
}

// ===========================================================================
extern "C" void kernel_launch(void* const* d_in, const int* in_sizes, int n_in,
                              void* d_out, int out_size) {
    const float* x   = (const float*)d_in[0];   // (64,64,64,64)
    const float* off = (const float*)d_in[1];   // (1,256,64,3,3)
    float* out       = (float*)d_out;           // (64,256,32,32)

    k_border<<<1056, 256>>>();
    dim3 gx(64, 64);                            // (h, b)
    k_prep_x<<<gx, 256>>>(x);
    k_prep_o<<<576, 256>>>(off);

    cudaFuncSetAttribute(k_mex, cudaFuncAttributeMaxDynamicSharedMemorySize, SMEM_TOTAL);
    k_mex<<<512, NTHR, SMEM_TOTAL>>>(out);
}

// round 7
// speedup vs baseline: 5.9317x; 1.1822x over previous
#include <cuda_runtime.h>
#include <cuda_fp16.h>
#include <cstdint>
#include <math.h>

// ---------------- problem constants ----------------
#define NB    64
#define NCH   64
#define NI    256
#define NKTOT 576          // 64 ch * 9 taps ; reordered k' = r*64 + c
#define PADW  66           // (H+2) halo for pad-1
#define LNK   6.35610766f  // ln(576)

// ---------------- GEMM tiling ----------------
// CTA tile 128(M) x 128(N); stage = { A_hi 16KB | A_lo 16KB | B 16KB }
#define STAGES   2
#define AOFF_LO  16384
#define BOFF     32768
#define STG_SZ   49152
#define SMEM_TOTAL (STAGES * STG_SZ)            // 98304 -> 2 CTAs/SM
#define NTHR     128

// ---------------- device scratch (allocation-free rule) ----------------
__device__ __align__(16) __half g_eh[(size_t)NB * PADW * PADW * NCH]; // exp(x) hi
__device__ __align__(16) __half g_el[(size_t)NB * PADW * PADW * NCH]; // exp(x) lo
__device__ __align__(16) __half g_Bh[NI * NKTOT];                     // exp(off) hi [i][r*64+c]

// ---------------- helpers ----------------
__device__ __forceinline__ uint32_t smem_u32(const void* p) {
    uint32_t a;
    asm("{ .reg .u64 t; cvta.to.shared.u64 t, %1; cvt.u32.u64 %0, t; }" : "=r"(a) : "l"(p));
    return a;
}
__device__ __forceinline__ uint32_t swz(uint32_t o) { return o ^ ((o >> 3) & 0x70); }

__device__ __forceinline__ void cp16(uint32_t dst, const void* src) {
    asm volatile("cp.async.cg.shared.global [%0], [%1], 16;" :: "r"(dst), "l"(src));
}

#define LDSM4(r, a)                                                                     \
    asm volatile("ldmatrix.sync.aligned.m8n8.x4.shared.b16 {%0,%1,%2,%3}, [%4];"        \
        : "=r"((r)[0]), "=r"((r)[1]), "=r"((r)[2]), "=r"((r)[3]) : "r"(a))

#define MMA16816(d, a, b0, b1)                                                          \
    asm volatile("mma.sync.aligned.m16n8k16.row.col.f32.f16.f16.f32 "                   \
        "{%0,%1,%2,%3}, {%4,%5,%6,%7}, {%8,%9}, {%0,%1,%2,%3};"                         \
        : "+f"((d)[0]), "+f"((d)[1]), "+f"((d)[2]), "+f"((d)[3])                        \
        : "r"((a)[0]), "r"((a)[1]), "r"((a)[2]), "r"((a)[3]), "r"(b0), "r"(b1))

// ===========================================================================
// Prep 1: halo borders, half2 stores (pad = exp(0)=1 -> hi=1, lo=0)
// ===========================================================================
__global__ void k_border() {
    int t = blockIdx.x * 256 + threadIdx.x;   // < 64*2*66*32 = 270336 half2's
    int c2   = t & 31;
    int rest = t >> 5;
    int pos  = rest % PADW;
    int be   = rest / PADW;
    int e = be & 1, b = be >> 1;
    size_t off2;
    if (e == 0) off2 = ((((size_t)b * PADW + 0) * PADW + pos) << 5) + c2;   // top row
    else        off2 = ((((size_t)b * PADW + pos) * PADW + 0) << 5) + c2;   // left col
    reinterpret_cast<__half2*>(g_eh)[off2] = __floats2half2_rn(1.0f, 1.0f);
    reinterpret_cast<__half2*>(g_el)[off2] = __floats2half2_rn(0.0f, 0.0f);
}

// ===========================================================================
// Prep 2: exp(x), fp16 hi/lo split, transpose (B,C,H,W) -> (B,H+2,W+2,C)
// ===========================================================================
__global__ void k_prep_x(const float* __restrict__ x) {
    __shared__ float tile[64][66];            // [w][c]
    const int b = blockIdx.y, h = blockIdx.x, t = threadIdx.x;
#pragma unroll
    for (int i = 0; i < 16; ++i) {
        int idx = t + i * 256;
        int c = idx >> 6, w = idx & 63;
        tile[w][c] = x[(((size_t)(b * 64 + c) * 64 + h) << 6) + w];
    }
    __syncthreads();
#pragma unroll
    for (int i = 0; i < 8; ++i) {
        int idx = t + i * 256;                // 2048 half2's
        int w = idx >> 5, c2 = idx & 31;
        float2 v = *reinterpret_cast<const float2*>(&tile[w][2 * c2]);
        float e0 = __expf(v.x), e1 = __expf(v.y);
        __half h0 = __float2half_rn(e0), h1 = __float2half_rn(e1);
        float l0 = e0 - __half2float(h0), l1 = e1 - __half2float(h1);
        size_t off2 = ((((size_t)b * PADW + (h + 1)) * PADW + (w + 1)) << 5) + c2;
        reinterpret_cast<__half2*>(g_eh)[off2] = __halves2half2(h0, h1);
        reinterpret_cast<__half2*>(g_el)[off2] = __floats2half2_rn(l0, l1);
    }
}

// ===========================================================================
// Prep 3: exp(offsets) fp16, reorder k = c*9+r  ->  k' = r*64+c
// ===========================================================================
__global__ void k_prep_o(const float* __restrict__ off) {
    int t = blockIdx.x * 256 + threadIdx.x;  // < 256*576 = 147456
    int i  = t / NKTOT;
    int kp = t - i * NKTOT;
    int r = kp >> 6, c = kp & 63;
    g_Bh[t] = __float2half_rn(__expf(off[i * NKTOT + c * 9 + r]));
}

// ===========================================================================
// Main GEMM: CTA 128(M) x 128(N), 4 warps 2x2, warp tile 64x64.
// 9 taps; per tap: hi pass (A_hi*B) + lo pass (A_lo*B), B frags reused.
// 2 CTAs/SM for barrier overlap.
// ===========================================================================
__device__ __forceinline__ void load_chunk(int r, int s, uint32_t smb,
                                           int tid, int bb, int ohb, int nbase) {
    int fh = r / 3, fw = r - fh * 3;
    uint32_t sah = smb + s * STG_SZ;
    uint32_t sal = sah + AOFF_LO;
    uint32_t sb  = sah + BOFF;
    // A tiles (hi & lo): 128 rows x 8 segs = 1024 x 16B each
#pragma unroll
    for (int it = 0; it < 8; ++it) {
        int idx = tid + it * NTHR;
        int l = idx >> 3, g = idx & 7;
        int ih1 = 2 * ohb + ((l >> 5) << 1) + fh;   // (oh*2-1+fh)+1
        int iw1 = ((l & 31) << 1) + fw;             // (ow*2-1+fw)+1
        size_t eo = ((((size_t)bb * PADW + ih1) * PADW + iw1) << 6) + (g << 3);
        uint32_t so = swz((l << 7) + (g << 4));
        cp16(sah + so, g_eh + eo);
        cp16(sal + so, g_el + eo);
    }
    // B tile: 128 rows x 8 segs = 1024 x 16B
#pragma unroll
    for (int it = 0; it < 8; ++it) {
        int idx = tid + it * NTHR;
        int n = idx >> 3, g = idx & 7;
        const void* src = g_Bh + (size_t)(nbase + n) * NKTOT + (r << 6) + (g << 3);
        cp16(sb + swz((n << 7) + (g << 4)), src);
    }
    asm volatile("cp.async.commit_group;" ::: "memory");
}

__global__ void __launch_bounds__(NTHR, 2) k_mex(float* __restrict__ out) {
    extern __shared__ __align__(1024) char sm[];
    const uint32_t smb = smem_u32(sm);
    const int tid  = threadIdx.x;
    const int wid  = tid >> 5, lane = tid & 31;
    const int bx   = blockIdx.x;
    const int bb   = bx >> 4;                   // batch
    const int ohb  = ((bx >> 1) & 7) << 2;      // 4 output rows per tile
    const int nh   = bx & 1;                    // instance half
    const int nbase = nh << 7;
    const int wm   = wid >> 1;                  // 0..1  (m block of 64)
    const int wn   = wid & 1;                   // 0..1  (n block of 64)

    float acc[4][8][4];                          // [mt][n8 tile][d-regs]
#pragma unroll
    for (int a = 0; a < 4; ++a)
#pragma unroll
        for (int b = 0; b < 8; ++b)
#pragma unroll
            for (int c = 0; c < 4; ++c) acc[a][b][c] = 0.0f;

    // per-lane ldmatrix address components
    const int rowA_l = (lane & 7) + (lane & 8);        // + mt*16 + wm*64
    const int segA_l = (lane & 16);                    // + ks*32
    const int rowB_l = (lane & 7) + ((lane & 16) >> 1);// + jj*16 + wn*64
    const int segB_l = ((lane & 8) << 1);              // + ks*32

    // prologue: prefetch tap 0
    load_chunk(0, 0, smb, tid, bb, ohb, nbase);

#pragma unroll 1
    for (int j = 0; j < 9; ++j) {
        asm volatile("cp.async.wait_group 0;" ::: "memory");
        __syncthreads();     // chunk j ready; all threads done with chunk j-1

        if (j + 1 < 9) load_chunk(j + 1, (j + 1) & 1, smb, tid, bb, ohb, nbase);

        const uint32_t sah = smb + (j & 1) * STG_SZ;
        const uint32_t sal = sah + AOFF_LO;
        const uint32_t sb  = sah + BOFF;

#pragma unroll
        for (int ks = 0; ks < 4; ++ks) {
            uint32_t bf[4][4];
#pragma unroll
            for (int jj = 0; jj < 4; ++jj) {
                int row = wn * 64 + jj * 16 + rowB_l;
                uint32_t byo = (uint32_t)(ks * 32 + segB_l) ^ ((row & 7) << 4);
                LDSM4(bf[jj], sb + row * 128 + byo);
            }
#pragma unroll
            for (int mt = 0; mt < 4; ++mt) {
                int row = wm * 64 + mt * 16 + rowA_l;
                uint32_t byo = (uint32_t)(ks * 32 + segA_l) ^ ((row & 7) << 4);
                uint32_t af[4];
                LDSM4(af, sah + row * 128 + byo);       // hi pass
#pragma unroll
                for (int jj = 0; jj < 4; ++jj) {
                    MMA16816(acc[mt][2 * jj],     af, bf[jj][0], bf[jj][1]);
                    MMA16816(acc[mt][2 * jj + 1], af, bf[jj][2], bf[jj][3]);
                }
                LDSM4(af, sal + row * 128 + byo);       // lo pass (same B)
#pragma unroll
                for (int jj = 0; jj < 4; ++jj) {
                    MMA16816(acc[mt][2 * jj],     af, bf[jj][0], bf[jj][1]);
                    MMA16816(acc[mt][2 * jj + 1], af, bf[jj][2], bf[jj][3]);
                }
            }
        }
    }

    // epilogue: y = log(S) - ln(576); out layout (B, NI, 32, 32)
    const int g  = lane >> 2;
    const int tc = lane & 3;
    float* ob = out + ((size_t)bb << 18);
#pragma unroll
    for (int mt = 0; mt < 4; ++mt) {
#pragma unroll
        for (int jj = 0; jj < 8; ++jj) {
            const int i0 = nbase + wn * 64 + jj * 8 + 2 * tc;
#pragma unroll
            for (int r = 0; r < 4; ++r) {
                int m = wm * 64 + mt * 16 + g + ((r >> 1) << 3);
                int i = i0 + (r & 1);
                float y = __logf(acc[mt][jj][r]) - LNK;
                ob[((size_t)i << 10) + ((ohb + (m >> 5)) << 5) + (m & 31)] = y;
            }
        }
    }
}

// ===========================================================================
extern "C" void kernel_launch(void* const* d_in, const int* in_sizes, int n_in,
                              void* d_out, int out_size) {
    const float* x   = (const float*)d_in[0];   // (64,64,64,64)
    const float* off = (const float*)d_in[1];   // (1,256,64,3,3)
    float* out       = (float*)d_out;           // (64,256,32,32)

    k_border<<<1056, 256>>>();
    dim3 gx(64, 64);                            // (h, b)
    k_prep_x<<<gx, 256>>>(x);
    k_prep_o<<<576, 256>>>(off);

    cudaFuncSetAttribute(k_mex, cudaFuncAttributeMaxDynamicSharedMemorySize, SMEM_TOTAL);
    k_mex<<<1024, NTHR, SMEM_TOTAL>>>(out);
}

// round 8
// speedup vs baseline: 8.3958x; 1.4154x over previous
#include <cuda_runtime.h>
#include <cuda_fp16.h>
#include <cstdint>
#include <math.h>

// ---------------- problem constants ----------------
#define NB    64
#define NCH   64
#define NI    256
#define NKTOT 576          // 64 ch * 9 taps ; reordered k' = r*64 + c
#define PADW  66           // (H+2) halo for pad-1
#define LNK   6.35610766f  // ln(576)

// ---------------- GEMM tiling ----------------
// CTA tile 128(M) x 128(N); stage = { A 16KB | B 16KB }
#define STAGES   3
#define BOFF     16384
#define STG_SZ   32768
#define SMEM_TOTAL (STAGES * STG_SZ)            // 98304 -> 2 CTAs/SM
#define NTHR     128

// ---------------- device scratch (allocation-free rule) ----------------
__device__ __align__(16) __half g_eh[(size_t)NB * PADW * PADW * NCH]; // exp(x) fp16
__device__ __align__(16) __half g_Bh[NI * NKTOT];                     // exp(off) fp16 [i][r*64+c]

// ---------------- helpers ----------------
__device__ __forceinline__ uint32_t smem_u32(const void* p) {
    uint32_t a;
    asm("{ .reg .u64 t; cvta.to.shared.u64 t, %1; cvt.u32.u64 %0, t; }" : "=r"(a) : "l"(p));
    return a;
}
__device__ __forceinline__ uint32_t swz(uint32_t o) { return o ^ ((o >> 3) & 0x70); }

__device__ __forceinline__ void cp16(uint32_t dst, const void* src) {
    asm volatile("cp.async.cg.shared.global [%0], [%1], 16;" :: "r"(dst), "l"(src));
}

#define LDSM4(r, a)                                                                     \
    asm volatile("ldmatrix.sync.aligned.m8n8.x4.shared.b16 {%0,%1,%2,%3}, [%4];"        \
        : "=r"((r)[0]), "=r"((r)[1]), "=r"((r)[2]), "=r"((r)[3]) : "r"(a))

#define MMA16816(d, a, b0, b1)                                                          \
    asm volatile("mma.sync.aligned.m16n8k16.row.col.f32.f16.f16.f32 "                   \
        "{%0,%1,%2,%3}, {%4,%5,%6,%7}, {%8,%9}, {%0,%1,%2,%3};"                         \
        : "+f"((d)[0]), "+f"((d)[1]), "+f"((d)[2]), "+f"((d)[3])                        \
        : "r"((a)[0]), "r"((a)[1]), "r"((a)[2]), "r"((a)[3]), "r"(b0), "r"(b1))

// ===========================================================================
// Prep 1: halo borders, half2 stores (pad = exp(0)=1)
// ===========================================================================
__global__ void k_border() {
    int t = blockIdx.x * 256 + threadIdx.x;   // < 64*2*66*32 = 270336 half2's
    int c2   = t & 31;
    int rest = t >> 5;
    int pos  = rest % PADW;
    int be   = rest / PADW;
    int e = be & 1, b = be >> 1;
    size_t off2;
    if (e == 0) off2 = ((((size_t)b * PADW + 0) * PADW + pos) << 5) + c2;   // top row
    else        off2 = ((((size_t)b * PADW + pos) * PADW + 0) << 5) + c2;   // left col
    reinterpret_cast<__half2*>(g_eh)[off2] = __floats2half2_rn(1.0f, 1.0f);
}

// ===========================================================================
// Prep 2: exp(x) fp16, transpose (B,C,H,W) -> (B,H+2,W+2,C)
// ===========================================================================
__global__ void k_prep_x(const float* __restrict__ x) {
    __shared__ float tile[64][66];            // [w][c]
    const int b = blockIdx.y, h = blockIdx.x, t = threadIdx.x;
#pragma unroll
    for (int i = 0; i < 16; ++i) {
        int idx = t + i * 256;
        int c = idx >> 6, w = idx & 63;
        tile[w][c] = x[(((size_t)(b * 64 + c) * 64 + h) << 6) + w];
    }
    __syncthreads();
#pragma unroll
    for (int i = 0; i < 8; ++i) {
        int idx = t + i * 256;                // 2048 half2's
        int w = idx >> 5, c2 = idx & 31;
        float2 v = *reinterpret_cast<const float2*>(&tile[w][2 * c2]);
        size_t off2 = ((((size_t)b * PADW + (h + 1)) * PADW + (w + 1)) << 5) + c2;
        reinterpret_cast<__half2*>(g_eh)[off2] =
            __floats2half2_rn(__expf(v.x), __expf(v.y));
    }
}

// ===========================================================================
// Prep 3: exp(offsets) fp16, reorder k = c*9+r  ->  k' = r*64+c
// ===========================================================================
__global__ void k_prep_o(const float* __restrict__ off) {
    int t = blockIdx.x * 256 + threadIdx.x;  // < 256*576 = 147456
    int i  = t / NKTOT;
    int kp = t - i * NKTOT;
    int r = kp >> 6, c = kp & 63;
    g_Bh[t] = __float2half_rn(__expf(off[i * NKTOT + c * 9 + r]));
}

// ===========================================================================
// Main GEMM: CTA 128(M) x 128(N), 4 warps 2x2, warp tile 64x64.
// Single fp16 pass, 9 taps (K-chunks of 64). 2 CTAs/SM, 3-stage pipeline.
// ===========================================================================
__device__ __forceinline__ void load_chunk(int r, int s, uint32_t smb,
                                           int tid, int bb, int ohb, int nbase) {
    int fh = r / 3, fw = r - fh * 3;
    uint32_t sa = smb + s * STG_SZ;
    uint32_t sb = sa + BOFF;
    // A tile: 128 rows x 8 segs = 1024 x 16B
#pragma unroll
    for (int it = 0; it < 8; ++it) {
        int idx = tid + it * NTHR;
        int l = idx >> 3, g = idx & 7;
        int ih1 = 2 * ohb + ((l >> 5) << 1) + fh;   // (oh*2-1+fh)+1
        int iw1 = ((l & 31) << 1) + fw;             // (ow*2-1+fw)+1
        size_t eo = ((((size_t)bb * PADW + ih1) * PADW + iw1) << 6) + (g << 3);
        cp16(sa + swz((l << 7) + (g << 4)), g_eh + eo);
    }
    // B tile: 128 rows x 8 segs = 1024 x 16B
#pragma unroll
    for (int it = 0; it < 8; ++it) {
        int idx = tid + it * NTHR;
        int n = idx >> 3, g = idx & 7;
        const void* src = g_Bh + (size_t)(nbase + n) * NKTOT + (r << 6) + (g << 3);
        cp16(sb + swz((n << 7) + (g << 4)), src);
    }
    asm volatile("cp.async.commit_group;" ::: "memory");
}

__global__ void __launch_bounds__(NTHR, 2) k_mex(float* __restrict__ out) {
    extern __shared__ __align__(1024) char sm[];
    const uint32_t smb = smem_u32(sm);
    const int tid  = threadIdx.x;
    const int wid  = tid >> 5, lane = tid & 31;
    const int bx   = blockIdx.x;
    const int bb   = bx >> 4;                   // batch
    const int ohb  = ((bx >> 1) & 7) << 2;      // 4 output rows per tile
    const int nbase = (bx & 1) << 7;            // instance half
    const int wm   = wid >> 1;                  // 0..1  (m block of 64)
    const int wn   = wid & 1;                   // 0..1  (n block of 64)

    float acc[4][8][4];                          // [mt][n8 tile][d-regs]
#pragma unroll
    for (int a = 0; a < 4; ++a)
#pragma unroll
        for (int b = 0; b < 8; ++b)
#pragma unroll
            for (int c = 0; c < 4; ++c) acc[a][b][c] = 0.0f;

    // per-lane ldmatrix address components
    const int rowA_l = (lane & 7) + (lane & 8);        // + mt*16 + wm*64
    const int segA_l = (lane & 16);                    // + ks*32
    const int rowB_l = (lane & 7) + ((lane & 16) >> 1);// + jj*16 + wn*64
    const int segB_l = ((lane & 8) << 1);              // + ks*32

    // prologue: prefetch taps 0,1
    load_chunk(0, 0, smb, tid, bb, ohb, nbase);
    load_chunk(1, 1, smb, tid, bb, ohb, nbase);

#pragma unroll 1
    for (int j = 0; j < 9; ++j) {
        if (j < 8) asm volatile("cp.async.wait_group 1;" ::: "memory");
        else       asm volatile("cp.async.wait_group 0;" ::: "memory");
        __syncthreads();     // chunk j ready; all warps done with chunk j-1

        if (j + 2 < 9) load_chunk(j + 2, (j + 2) % 3, smb, tid, bb, ohb, nbase);

        const uint32_t sa = smb + (j % 3) * STG_SZ;
        const uint32_t sb = sa + BOFF;

#pragma unroll
        for (int ks = 0; ks < 4; ++ks) {
            uint32_t bf[4][4];
#pragma unroll
            for (int jj = 0; jj < 4; ++jj) {
                int row = wn * 64 + jj * 16 + rowB_l;
                uint32_t byo = (uint32_t)(ks * 32 + segB_l) ^ ((row & 7) << 4);
                LDSM4(bf[jj], sb + row * 128 + byo);
            }
#pragma unroll
            for (int mt = 0; mt < 4; ++mt) {
                int row = wm * 64 + mt * 16 + rowA_l;
                uint32_t byo = (uint32_t)(ks * 32 + segA_l) ^ ((row & 7) << 4);
                uint32_t af[4];
                LDSM4(af, sa + row * 128 + byo);
#pragma unroll
                for (int jj = 0; jj < 4; ++jj) {
                    MMA16816(acc[mt][2 * jj],     af, bf[jj][0], bf[jj][1]);
                    MMA16816(acc[mt][2 * jj + 1], af, bf[jj][2], bf[jj][3]);
                }
            }
        }
    }

    // epilogue: y = log(S) - ln(576); out layout (B, NI, 32, 32)
    const int g  = lane >> 2;
    const int tc = lane & 3;
    float* ob = out + ((size_t)bb << 18);
#pragma unroll
    for (int mt = 0; mt < 4; ++mt) {
#pragma unroll
        for (int jj = 0; jj < 8; ++jj) {
            const int i0 = nbase + wn * 64 + jj * 8 + 2 * tc;
#pragma unroll
            for (int r = 0; r < 4; ++r) {
                int m = wm * 64 + mt * 16 + g + ((r >> 1) << 3);
                int i = i0 + (r & 1);
                float y = __logf(acc[mt][jj][r]) - LNK;
                ob[((size_t)i << 10) + ((ohb + (m >> 5)) << 5) + (m & 31)] = y;
            }
        }
    }
}

// ===========================================================================
extern "C" void kernel_launch(void* const* d_in, const int* in_sizes, int n_in,
                              void* d_out, int out_size) {
    const float* x   = (const float*)d_in[0];   // (64,64,64,64)
    const float* off = (const float*)d_in[1];   // (1,256,64,3,3)
    float* out       = (float*)d_out;           // (64,256,32,32)

    k_border<<<1056, 256>>>();
    dim3 gx(64, 64);                            // (h, b)
    k_prep_x<<<gx, 256>>>(x);
    k_prep_o<<<576, 256>>>(off);

    cudaFuncSetAttribute(k_mex, cudaFuncAttributeMaxDynamicSharedMemorySize, SMEM_TOTAL);
    k_mex<<<1024, NTHR, SMEM_TOTAL>>>(out);
}